// round 1
// baseline (speedup 1.0000x reference)
#include <cuda_runtime.h>

#define NROWS 16384   // B*T
#define EDIM  1024
#define DDIM  64
#define BSZ   8
#define TSEQ  2048

// Scratch for projected Q, K, V (device globals: allocation-free)
__device__ float g_q[NROWS * DDIM];
__device__ float g_k[NROWS * DDIM];
__device__ float g_v[NROWS * DDIM];

// ---------------------------------------------------------------------------
// Projection GEMM: out[m][d] = sum_e x[m][e] * W[d][e]
// Tile: 128 rows x 64 cols (all of D), BK=32. 256 threads, 8x4 microtile.
// blockIdx.y in {0,1,2} selects (Wq->g_q, Wk->g_k, Wv->g_v).
// ---------------------------------------------------------------------------
__global__ __launch_bounds__(256) void proj_kernel(
    const float* __restrict__ x,
    const float* __restrict__ Wq,
    const float* __restrict__ Wk,
    const float* __restrict__ Wv)
{
    __shared__ float xs[32][132];  // [k][m], +4 pad
    __shared__ float ws[32][68];   // [k][d], +4 pad

    const float* W  = (blockIdx.y == 0) ? Wq : (blockIdx.y == 1) ? Wk : Wv;
    float*       out = (blockIdx.y == 0) ? g_q : (blockIdx.y == 1) ? g_k : g_v;

    const int tid = threadIdx.x;
    const int tx  = tid & 15;   // col group (4 cols each)
    const int ty  = tid >> 4;   // row group (8 rows each)
    const int m0  = blockIdx.x * 128;

    float acc[8][4];
#pragma unroll
    for (int r = 0; r < 8; r++)
#pragma unroll
        for (int c = 0; c < 4; c++) acc[r][c] = 0.f;

    for (int k0 = 0; k0 < EDIM; k0 += 32) {
        // load x tile (coalesced float4 along k, store transposed)
#pragma unroll
        for (int i = 0; i < 4; i++) {
            int slot = tid + i * 256;           // 1024 float4 slots
            int m = slot >> 3, j = slot & 7;
            float4 v = *(const float4*)&x[(size_t)(m0 + m) * EDIM + k0 + 4 * j];
            xs[4 * j + 0][m] = v.x; xs[4 * j + 1][m] = v.y;
            xs[4 * j + 2][m] = v.z; xs[4 * j + 3][m] = v.w;
        }
        // load W tile
#pragma unroll
        for (int i = 0; i < 2; i++) {
            int slot = tid + i * 256;           // 512 float4 slots
            int d = slot >> 3, j = slot & 7;
            float4 v = *(const float4*)&W[(size_t)d * EDIM + k0 + 4 * j];
            ws[4 * j + 0][d] = v.x; ws[4 * j + 1][d] = v.y;
            ws[4 * j + 2][d] = v.z; ws[4 * j + 3][d] = v.w;
        }
        __syncthreads();

#pragma unroll
        for (int k = 0; k < 32; k++) {
            float4 b4 = *(const float4*)&ws[k][tx * 4];
            float4 a0 = *(const float4*)&xs[k][ty * 8];
            float4 a1 = *(const float4*)&xs[k][ty * 8 + 4];
            float a[8] = {a0.x, a0.y, a0.z, a0.w, a1.x, a1.y, a1.z, a1.w};
            float b[4] = {b4.x, b4.y, b4.z, b4.w};
#pragma unroll
            for (int r = 0; r < 8; r++)
#pragma unroll
                for (int c = 0; c < 4; c++) acc[r][c] += a[r] * b[c];
        }
        __syncthreads();
    }

#pragma unroll
    for (int r = 0; r < 8; r++) {
        float4 v = make_float4(acc[r][0], acc[r][1], acc[r][2], acc[r][3]);
        *(float4*)&out[(size_t)(m0 + ty * 8 + r) * DDIM + tx * 4] = v;
    }
}

// ---------------------------------------------------------------------------
// Flash attention: one block per (batch, 64-row query tile).
// 256 threads; 4x4 per-thread tiles for both S=Q*K^T and O+=P*V.
// Online softmax; causal tile skip (kt <= qt only).
// ---------------------------------------------------------------------------
__global__ __launch_bounds__(256) void attn_kernel(float* __restrict__ out)
{
    extern __shared__ float smem[];
    float (*Qs)[68] = (float(*)[68])(smem);
    float (*Ks)[68] = (float(*)[68])(smem + 64 * 68);
    float (*Vs)[68] = (float(*)[68])(smem + 2 * 64 * 68);
    float (*Ps)[68] = (float(*)[68])(smem + 3 * 64 * 68);

    const int tid = threadIdx.x;
    const int tx  = tid & 15;   // score-col / D-col group (4 each)
    const int ty  = tid >> 4;   // row group (4 each)
    const int b   = blockIdx.y;
    const int qt  = gridDim.x - 1 - blockIdx.x;  // schedule big tiles first
    const int q0  = qt * 64;
    const size_t base = (size_t)b * TSEQ * DDIM;

    const float scale = 0.125f;  // 1/sqrt(64)

    // load Q tile (pre-scaled)
#pragma unroll
    for (int i = 0; i < 4; i++) {
        int slot = tid + i * 256;          // 1024 float4 slots (64x16)
        int m = slot >> 4, j = slot & 15;
        float4 v = *(const float4*)&g_q[base + (size_t)(q0 + m) * DDIM + 4 * j];
        v.x *= scale; v.y *= scale; v.z *= scale; v.w *= scale;
        *(float4*)&Qs[m][4 * j] = v;
    }

    float m_i[4], l_i[4], O[4][4];
#pragma unroll
    for (int r = 0; r < 4; r++) {
        m_i[r] = -1e30f; l_i[r] = 0.f;
#pragma unroll
        for (int c = 0; c < 4; c++) O[r][c] = 0.f;
    }

    for (int kt = 0; kt <= qt; kt++) {
        __syncthreads();  // previous O-GEMM done reading Ps/Vs
        const int k0 = kt * 64;
#pragma unroll
        for (int i = 0; i < 4; i++) {
            int slot = tid + i * 256;
            int m = slot >> 4, j = slot & 15;
            *(float4*)&Ks[m][4 * j] =
                *(const float4*)&g_k[base + (size_t)(k0 + m) * DDIM + 4 * j];
            *(float4*)&Vs[m][4 * j] =
                *(const float4*)&g_v[base + (size_t)(k0 + m) * DDIM + 4 * j];
        }
        __syncthreads();

        // S = Q * K^T  (4x4 per thread)
        float s[4][4];
#pragma unroll
        for (int r = 0; r < 4; r++)
#pragma unroll
            for (int c = 0; c < 4; c++) s[r][c] = 0.f;

#pragma unroll
        for (int d = 0; d < 64; d += 4) {
            float a[4][4], kk[4][4];
#pragma unroll
            for (int r = 0; r < 4; r++) {
                float4 t = *(const float4*)&Qs[ty * 4 + r][d];
                a[r][0] = t.x; a[r][1] = t.y; a[r][2] = t.z; a[r][3] = t.w;
            }
#pragma unroll
            for (int c = 0; c < 4; c++) {
                float4 t = *(const float4*)&Ks[tx * 4 + c][d];
                kk[c][0] = t.x; kk[c][1] = t.y; kk[c][2] = t.z; kk[c][3] = t.w;
            }
#pragma unroll
            for (int r = 0; r < 4; r++)
#pragma unroll
                for (int c = 0; c < 4; c++)
                    s[r][c] += a[r][0] * kk[c][0] + a[r][1] * kk[c][1] +
                               a[r][2] * kk[c][2] + a[r][3] * kk[c][3];
        }

        if (kt == qt) {  // causal mask on diagonal tile (k0 == q0)
#pragma unroll
            for (int r = 0; r < 4; r++)
#pragma unroll
                for (int c = 0; c < 4; c++)
                    if (tx * 4 + c > ty * 4 + r) s[r][c] = -1e30f;
        }

        // online softmax per row (reduce across the 16 tx lanes; a ty group
        // occupies lanes [g*16, g*16+16) within a warp, so xor masks 8..1 stay inside)
#pragma unroll
        for (int r = 0; r < 4; r++) {
            float rmax = fmaxf(fmaxf(s[r][0], s[r][1]), fmaxf(s[r][2], s[r][3]));
#pragma unroll
            for (int w = 8; w >= 1; w >>= 1)
                rmax = fmaxf(rmax, __shfl_xor_sync(0xffffffffu, rmax, w));
            float newm  = fmaxf(m_i[r], rmax);
            float alpha = __expf(m_i[r] - newm);
            float rsum = 0.f;
#pragma unroll
            for (int c = 0; c < 4; c++) {
                s[r][c] = __expf(s[r][c] - newm);
                rsum += s[r][c];
            }
#pragma unroll
            for (int w = 8; w >= 1; w >>= 1)
                rsum += __shfl_xor_sync(0xffffffffu, rsum, w);
            l_i[r] = l_i[r] * alpha + rsum;
            m_i[r] = newm;
#pragma unroll
            for (int c = 0; c < 4; c++) O[r][c] *= alpha;
            *(float4*)&Ps[ty * 4 + r][tx * 4] =
                make_float4(s[r][0], s[r][1], s[r][2], s[r][3]);
        }
        __syncthreads();

        // O += P * V  (4x4 per thread; D-cols = tx*4..tx*4+3)
#pragma unroll
        for (int j = 0; j < 64; j += 4) {
            float p[4][4], v[4][4];
#pragma unroll
            for (int r = 0; r < 4; r++) {
                float4 t = *(const float4*)&Ps[ty * 4 + r][j];
                p[r][0] = t.x; p[r][1] = t.y; p[r][2] = t.z; p[r][3] = t.w;
            }
#pragma unroll
            for (int jj = 0; jj < 4; jj++) {
                float4 t = *(const float4*)&Vs[j + jj][tx * 4];
                v[jj][0] = t.x; v[jj][1] = t.y; v[jj][2] = t.z; v[jj][3] = t.w;
            }
#pragma unroll
            for (int r = 0; r < 4; r++)
#pragma unroll
                for (int c = 0; c < 4; c++)
                    O[r][c] += p[r][0] * v[0][c] + p[r][1] * v[1][c] +
                               p[r][2] * v[2][c] + p[r][3] * v[3][c];
        }
    }

    // epilogue: normalize and store
#pragma unroll
    for (int r = 0; r < 4; r++) {
        float inv = 1.f / l_i[r];
        float4 o = make_float4(O[r][0] * inv, O[r][1] * inv,
                               O[r][2] * inv, O[r][3] * inv);
        *(float4*)&out[base + (size_t)(q0 + ty * 4 + r) * DDIM + tx * 4] = o;
    }
}

// ---------------------------------------------------------------------------
// Launch
// ---------------------------------------------------------------------------
extern "C" void kernel_launch(void* const* d_in, const int* in_sizes, int n_in,
                              void* d_out, int out_size)
{
    const float* x  = (const float*)d_in[0];
    const float* Wk = (const float*)d_in[1];
    const float* Wq = (const float*)d_in[2];
    const float* Wv = (const float*)d_in[3];
    float* out = (float*)d_out;

    // QKV projections: 128-row tiles x 3 weights
    proj_kernel<<<dim3(NROWS / 128, 3), 256>>>(x, Wq, Wk, Wv);

    // Flash attention: 32 query tiles x 8 batches
    const int SMEM_BYTES = 4 * 64 * 68 * sizeof(float);  // 69632
    cudaFuncSetAttribute(attn_kernel,
                         cudaFuncAttributeMaxDynamicSharedMemorySize, SMEM_BYTES);
    attn_kernel<<<dim3(TSEQ / 64, BSZ), 256, SMEM_BYTES>>>(out);
}

// round 2
// speedup vs baseline: 3.0788x; 3.0788x over previous
#include <cuda_runtime.h>

#define NROWS 16384   // B*T
#define EDIM  1024
#define DDIM  64
#define BSZ   8
#define TSEQ  2048
#define QT    32      // attention q-tile rows
#define KT    64      // attention kv-tile rows

// Scratch for projected Q, K, V (device globals: allocation-free)
__device__ float g_q[NROWS * DDIM];
__device__ float g_k[NROWS * DDIM];
__device__ float g_v[NROWS * DDIM];

// ---------------------------------------------------------------------------
// helpers
// ---------------------------------------------------------------------------
__device__ __forceinline__ unsigned f2tf(float x) {
    unsigned r;
    asm("cvt.rna.tf32.f32 %0, %1;" : "=r"(r) : "f"(x));
    return r;
}

// D = A(16x8,row) * B(8x8,col) + D, tf32 in, f32 accum
__device__ __forceinline__ void mma8(float c[4], const unsigned a[4],
                                     unsigned b0, unsigned b1) {
    asm volatile(
        "mma.sync.aligned.m16n8k8.row.col.f32.tf32.tf32.f32 "
        "{%0,%1,%2,%3},{%4,%5,%6,%7},{%8,%9},{%0,%1,%2,%3};\n"
        : "+f"(c[0]), "+f"(c[1]), "+f"(c[2]), "+f"(c[3])
        : "r"(a[0]), "r"(a[1]), "r"(a[2]), "r"(a[3]), "r"(b0), "r"(b1));
}

// exp(x) for x <= ~1, FMA-pipe only (no MUFU). deg-5 poly, rel err < 3e-6.
__device__ __forceinline__ float fast_exp(float x) {
    float t = x * 1.4426950408889634f;      // log2(e)
    t = fmaxf(t, -126.0f);                  // masked (-1e30) -> ~2^-126 = 0
    float tr = t + 12582912.0f;             // 1.5*2^23: round-to-nearest int
    float fl = tr - 12582912.0f;
    float f  = t - fl;                      // f in [-0.5, 0.5]
    float p = 1.3333558146e-3f;             // ln2^5/120
    p = fmaf(p, f, 9.6181291076e-3f);       // ln2^4/24
    p = fmaf(p, f, 5.5504108664e-2f);       // ln2^3/6
    p = fmaf(p, f, 2.4022650696e-1f);       // ln2^2/2
    p = fmaf(p, f, 6.9314718056e-1f);       // ln2
    p = fmaf(p, f, 1.0f);
    int n = __float_as_int(tr) - 0x4B400000;        // integer part
    float s = __int_as_float((n + 127) << 23);      // 2^n
    return p * s;
}

// ---------------------------------------------------------------------------
// Projection GEMM (tf32 MMA): out[m][d] = sum_e x[m][e] * W[d][e]
// Block: 128 rows x 64 cols, 8 warps in 4(m) x 2(n), warptile 32x32.
// blockIdx.y selects weight/output.
// ---------------------------------------------------------------------------
__global__ __launch_bounds__(256) void proj_mma(
    const float* __restrict__ x,
    const float* __restrict__ Wq,
    const float* __restrict__ Wk,
    const float* __restrict__ Wv)
{
    __shared__ float xs[128][36];   // stride 36 ≡ 4 (mod 32): conflict-free frags
    __shared__ float ws[64][36];

    const float* W;
    float* out;
    if (blockIdx.y == 0)      { W = Wq; out = g_q; }
    else if (blockIdx.y == 1) { W = Wk; out = g_k; }
    else                      { W = Wv; out = g_v; }

    const int tid  = threadIdx.x;
    const int lane = tid & 31;
    const int wid  = tid >> 5;
    const int wm   = wid & 3;       // 4 m-warps
    const int wn   = wid >> 2;      // 2 n-warps
    const int r    = lane >> 2;     // groupID
    const int cq   = lane & 3;      // threadID in group
    const int m0   = blockIdx.x * 128;

    float acc[2][4][4] = {};        // [mt][nt][reg]

    for (int k0 = 0; k0 < EDIM; k0 += 32) {
#pragma unroll
        for (int i = 0; i < 4; i++) {
            int slot = tid + i * 256;          // 1024 float4 slots (128x8)
            int m = slot >> 3, j = slot & 7;
            float4 v = *(const float4*)&x[(size_t)(m0 + m) * EDIM + k0 + 4 * j];
            *(float2*)&xs[m][4 * j]     = make_float2(v.x, v.y);
            *(float2*)&xs[m][4 * j + 2] = make_float2(v.z, v.w);
        }
#pragma unroll
        for (int i = 0; i < 2; i++) {
            int slot = tid + i * 256;          // 512 float4 slots (64x8)
            int d = slot >> 3, j = slot & 7;
            float4 v = *(const float4*)&W[(size_t)d * EDIM + k0 + 4 * j];
            *(float2*)&ws[d][4 * j]     = make_float2(v.x, v.y);
            *(float2*)&ws[d][4 * j + 2] = make_float2(v.z, v.w);
        }
        __syncthreads();

#pragma unroll
        for (int ks = 0; ks < 4; ks++) {
            int k = ks * 8;
            unsigned a[2][4];
#pragma unroll
            for (int mt = 0; mt < 2; mt++) {
                int rb = wm * 32 + mt * 16;
                a[mt][0] = f2tf(xs[rb + r][k + cq]);
                a[mt][1] = f2tf(xs[rb + r + 8][k + cq]);
                a[mt][2] = f2tf(xs[rb + r][k + cq + 4]);
                a[mt][3] = f2tf(xs[rb + r + 8][k + cq + 4]);
            }
#pragma unroll
            for (int nt = 0; nt < 4; nt++) {
                int nb = wn * 32 + nt * 8 + r;
                unsigned b0 = f2tf(ws[nb][k + cq]);
                unsigned b1 = f2tf(ws[nb][k + cq + 4]);
                mma8(acc[0][nt], a[0], b0, b1);
                mma8(acc[1][nt], a[1], b0, b1);
            }
        }
        __syncthreads();
    }

#pragma unroll
    for (int mt = 0; mt < 2; mt++)
#pragma unroll
        for (int nt = 0; nt < 4; nt++) {
            int row = m0 + wm * 32 + mt * 16 + r;
            int col = wn * 32 + nt * 8 + 2 * cq;
            *(float2*)&out[(size_t)row * DDIM + col] =
                make_float2(acc[mt][nt][0], acc[mt][nt][1]);
            *(float2*)&out[(size_t)(row + 8) * DDIM + col] =
                make_float2(acc[mt][nt][2], acc[mt][nt][3]);
        }
}

// ---------------------------------------------------------------------------
// Flash attention (tf32 MMA): block = (batch, 32-row q-tile), 8 warps in
// 2(m) x 4(n), warptile 16x16 for both S=QK^T and O+=PV. Online softmax with
// fast_exp. Causal tile skip + in-tile masking on the last tile.
// ---------------------------------------------------------------------------
__global__ __launch_bounds__(256) void attn_mma(float* __restrict__ out)
{
    extern __shared__ float smbuf[];
    float (*Qs)[68] = (float(*)[68])smbuf;                       // 32x68
    float (*Ks)[68] = (float(*)[68])(smbuf + 32 * 68);           // 64x68
    float (*Vs)[72] = (float(*)[72])(smbuf + 32 * 68 + 64 * 68); // 64x72
    float (*Sp)[68] = (float(*)[68])(smbuf + 32 * 68 + 64 * 68 + 64 * 72);
    float* alphas = smbuf + 32 * 68 + 64 * 68 + 64 * 72 + 32 * 68;
    float* ls     = alphas + 32;

    const int tid  = threadIdx.x;
    const int lane = tid & 31;
    const int wid  = tid >> 5;
    const int wm   = wid & 1;       // 2 m-warps (rows)
    const int wn   = wid >> 1;      // 4 n-warps (cols)
    const int r    = lane >> 2;
    const int cq   = lane & 3;
    const int b    = blockIdx.y;
    const int qt   = gridDim.x - 1 - blockIdx.x;   // big tiles first
    const int q0   = qt * QT;
    const size_t base = (size_t)b * TSEQ * DDIM;

    // softmax ownership: row rr (8 threads per row, 8 cols each)
    const int rr = tid >> 3;
    const int gg = tid & 7;

    // load Q tile (pre-scaled by 1/sqrt(64))
#pragma unroll
    for (int i = 0; i < 2; i++) {
        int slot = tid + i * 256;               // 512 float4 slots (32x16)
        int m = slot >> 4, j = slot & 15;
        float4 v = *(const float4*)&g_q[base + (size_t)(q0 + m) * DDIM + 4 * j];
        v.x *= 0.125f; v.y *= 0.125f; v.z *= 0.125f; v.w *= 0.125f;
        *(float2*)&Qs[m][4 * j]     = make_float2(v.x, v.y);
        *(float2*)&Qs[m][4 * j + 2] = make_float2(v.z, v.w);
    }

    float O[2][4] = {};             // [nt][reg]
    float m_i = -1e30f, l_i = 0.f;

    const int ntiles = qt / 2 + 1;
    for (int kt = 0; kt < ntiles; kt++) {
        __syncthreads();            // prev PV done reading Sp/Vs
        const int k0 = kt * KT;
#pragma unroll
        for (int i = 0; i < 4; i++) {
            int slot = tid + i * 256;           // 1024 float4 slots (64x16)
            int m = slot >> 4, j = slot & 15;
            float4 kv = *(const float4*)&g_k[base + (size_t)(k0 + m) * DDIM + 4 * j];
            *(float2*)&Ks[m][4 * j]     = make_float2(kv.x, kv.y);
            *(float2*)&Ks[m][4 * j + 2] = make_float2(kv.z, kv.w);
            float4 vv = *(const float4*)&g_v[base + (size_t)(k0 + m) * DDIM + 4 * j];
            *(float4*)&Vs[m][4 * j] = vv;
        }
        __syncthreads();

        // ---- S = Q * K^T (32x64, k=64) ----
        float sacc[2][4] = {};
#pragma unroll
        for (int ks = 0; ks < 8; ks++) {
            int k = ks * 8;
            unsigned a[4];
            int rb = wm * 16;
            a[0] = f2tf(Qs[rb + r][k + cq]);
            a[1] = f2tf(Qs[rb + r + 8][k + cq]);
            a[2] = f2tf(Qs[rb + r][k + cq + 4]);
            a[3] = f2tf(Qs[rb + r + 8][k + cq + 4]);
#pragma unroll
            for (int nt = 0; nt < 2; nt++) {
                int nb = wn * 16 + nt * 8 + r;
                unsigned b0 = f2tf(Ks[nb][k + cq]);
                unsigned b1 = f2tf(Ks[nb][k + cq + 4]);
                mma8(sacc[nt], a, b0, b1);
            }
        }

        // ---- mask (last tile only) + write S to smem ----
        const bool lastt = (kt == ntiles - 1);
#pragma unroll
        for (int nt = 0; nt < 2; nt++) {
            int row0 = wm * 16 + r;
            int col  = wn * 16 + nt * 8 + 2 * cq;
            float s0 = sacc[nt][0], s1 = sacc[nt][1];
            float s2 = sacc[nt][2], s3 = sacc[nt][3];
            if (lastt) {
                int qg0 = q0 + row0, qg1 = qg0 + 8;
                int sg0 = k0 + col,  sg1 = sg0 + 1;
                if (sg0 > qg0) s0 = -1e30f;
                if (sg1 > qg0) s1 = -1e30f;
                if (sg0 > qg1) s2 = -1e30f;
                if (sg1 > qg1) s3 = -1e30f;
            }
            *(float2*)&Sp[row0][col]     = make_float2(s0, s1);
            *(float2*)&Sp[row0 + 8][col] = make_float2(s2, s3);
        }
        __syncthreads();

        // ---- online softmax (8 threads per row, shfl over 8-lane groups) ----
        {
            float4 v0 = *(float4*)&Sp[rr][gg * 8];
            float4 v1 = *(float4*)&Sp[rr][gg * 8 + 4];
            float tmax = fmaxf(fmaxf(fmaxf(v0.x, v0.y), fmaxf(v0.z, v0.w)),
                               fmaxf(fmaxf(v1.x, v1.y), fmaxf(v1.z, v1.w)));
#pragma unroll
            for (int w = 4; w >= 1; w >>= 1)
                tmax = fmaxf(tmax, __shfl_xor_sync(0xffffffffu, tmax, w));
            float newm  = fmaxf(m_i, tmax);
            float alpha = fast_exp(m_i - newm);
            float p0 = fast_exp(v0.x - newm), p1 = fast_exp(v0.y - newm);
            float p2 = fast_exp(v0.z - newm), p3 = fast_exp(v0.w - newm);
            float p4 = fast_exp(v1.x - newm), p5 = fast_exp(v1.y - newm);
            float p6 = fast_exp(v1.z - newm), p7 = fast_exp(v1.w - newm);
            float tsum = ((p0 + p1) + (p2 + p3)) + ((p4 + p5) + (p6 + p7));
#pragma unroll
            for (int w = 4; w >= 1; w >>= 1)
                tsum += __shfl_xor_sync(0xffffffffu, tsum, w);
            l_i = l_i * alpha + tsum;
            m_i = newm;
            *(float4*)&Sp[rr][gg * 8]     = make_float4(p0, p1, p2, p3);
            *(float4*)&Sp[rr][gg * 8 + 4] = make_float4(p4, p5, p6, p7);
            if (gg == 0) alphas[rr] = alpha;
        }
        __syncthreads();

        // ---- O = O*alpha + P*V ----
        {
            float al0 = alphas[wm * 16 + r];
            float al1 = alphas[wm * 16 + r + 8];
#pragma unroll
            for (int nt = 0; nt < 2; nt++) {
                O[nt][0] *= al0; O[nt][1] *= al0;
                O[nt][2] *= al1; O[nt][3] *= al1;
            }
#pragma unroll
            for (int ks = 0; ks < 8; ks++) {
                int k = ks * 8;
                unsigned a[4];
                int rb = wm * 16;
                a[0] = f2tf(Sp[rb + r][k + cq]);
                a[1] = f2tf(Sp[rb + r + 8][k + cq]);
                a[2] = f2tf(Sp[rb + r][k + cq + 4]);
                a[3] = f2tf(Sp[rb + r + 8][k + cq + 4]);
#pragma unroll
                for (int nt = 0; nt < 2; nt++) {
                    int nb = wn * 16 + nt * 8 + r;            // d column
                    unsigned b0 = f2tf(Vs[k + cq][nb]);
                    unsigned b1 = f2tf(Vs[k + cq + 4][nb]);
                    mma8(O[nt], a, b0, b1);
                }
            }
        }
    }

    // epilogue: normalize by l and store
    if (gg == 0) ls[rr] = l_i;
    __syncthreads();
    float il0 = 1.f / ls[wm * 16 + r];
    float il1 = 1.f / ls[wm * 16 + r + 8];
#pragma unroll
    for (int nt = 0; nt < 2; nt++) {
        int row = q0 + wm * 16 + r;
        int col = wn * 16 + nt * 8 + 2 * cq;
        *(float2*)&out[base + (size_t)row * DDIM + col] =
            make_float2(O[nt][0] * il0, O[nt][1] * il0);
        *(float2*)&out[base + (size_t)(row + 8) * DDIM + col] =
            make_float2(O[nt][2] * il1, O[nt][3] * il1);
    }
}

// ---------------------------------------------------------------------------
// Launch
// ---------------------------------------------------------------------------
extern "C" void kernel_launch(void* const* d_in, const int* in_sizes, int n_in,
                              void* d_out, int out_size)
{
    const float* x  = (const float*)d_in[0];
    const float* Wk = (const float*)d_in[1];
    const float* Wq = (const float*)d_in[2];
    const float* Wv = (const float*)d_in[3];
    float* out = (float*)d_out;

    proj_mma<<<dim3(NROWS / 128, 3), 256>>>(x, Wq, Wk, Wv);

    // smem: Qs(32x68) + Ks(64x68) + Vs(64x72) + Sp(32x68) + 64 floats
    const int SMEM_BYTES = (32 * 68 + 64 * 68 + 64 * 72 + 32 * 68 + 64) * 4;
    cudaFuncSetAttribute(attn_mma,
                         cudaFuncAttributeMaxDynamicSharedMemorySize, SMEM_BYTES);
    attn_mma<<<dim3(TSEQ / QT, BSZ), 256, SMEM_BYTES>>>(out);
}

// round 3
// speedup vs baseline: 3.8201x; 1.2408x over previous
#include <cuda_runtime.h>

#define NROWS 16384   // B*T
#define EDIM  1024
#define DDIM  64
#define BSZ   8
#define TSEQ  2048
#define QT    32      // attention q-tile rows
#define KT    64      // attention kv-tile rows

// Scratch for projected Q, K, V — stored ALREADY tf32-rounded (valid tf32 bit
// patterns in float storage), so attention needs no cvt on Q/K/V.
__device__ float g_q[NROWS * DDIM];
__device__ float g_k[NROWS * DDIM];
__device__ float g_v[NROWS * DDIM];

// ---------------------------------------------------------------------------
// helpers
// ---------------------------------------------------------------------------
__device__ __forceinline__ unsigned f2tf(float x) {
    unsigned r;
    asm("cvt.rna.tf32.f32 %0, %1;" : "=r"(r) : "f"(x));
    return r;
}

// D = A(16x8,row) * B(8x8,col) + D, tf32 in, f32 accum
__device__ __forceinline__ void mma8(float c[4], const unsigned a[4],
                                     unsigned b0, unsigned b1) {
    asm volatile(
        "mma.sync.aligned.m16n8k8.row.col.f32.tf32.tf32.f32 "
        "{%0,%1,%2,%3},{%4,%5,%6,%7},{%8,%9},{%0,%1,%2,%3};\n"
        : "+f"(c[0]), "+f"(c[1]), "+f"(c[2]), "+f"(c[3])
        : "r"(a[0]), "r"(a[1]), "r"(a[2]), "r"(a[3]), "r"(b0), "r"(b1));
}

// exp(x) for x <= ~1, FMA-pipe only (no MUFU). deg-5 poly, rel err < 3e-6.
__device__ __forceinline__ float fast_exp(float x) {
    float t = x * 1.4426950408889634f;
    t = fmaxf(t, -126.0f);
    float tr = t + 12582912.0f;             // 1.5*2^23 round trick
    float fl = tr - 12582912.0f;
    float f  = t - fl;
    float p = 1.3333558146e-3f;
    p = fmaf(p, f, 9.6181291076e-3f);
    p = fmaf(p, f, 5.5504108664e-2f);
    p = fmaf(p, f, 2.4022650696e-1f);
    p = fmaf(p, f, 6.9314718056e-1f);
    p = fmaf(p, f, 1.0f);
    int n = __float_as_int(tr) - 0x4B400000;
    float s = __int_as_float((n + 127) << 23);
    return p * s;
}

// ---------------------------------------------------------------------------
// Merged projection GEMM (tf32 MMA): one block computes a 128-row slab of
// ALL THREE outputs (q,k,v), so the x tile is loaded+converted once.
// 8 warps in 4(m) x 2(n); per output each warp does a 32x32 warptile.
// Grid = 128 blocks (one wave). Epilogue stores tf32-rounded floats.
// ---------------------------------------------------------------------------
__global__ __launch_bounds__(256) void proj_mma(
    const float* __restrict__ x,
    const float* __restrict__ Wq,
    const float* __restrict__ Wk,
    const float* __restrict__ Wv)
{
    __shared__ unsigned xs[128][36];     // tf32 bits; stride 36 ≡ 4 (mod 32)
    __shared__ unsigned ws[3][64][36];

    const int tid  = threadIdx.x;
    const int lane = tid & 31;
    const int wid  = tid >> 5;
    const int wm   = wid & 3;
    const int wn   = wid >> 2;
    const int r    = lane >> 2;
    const int cq   = lane & 3;
    const int m0   = blockIdx.x * 128;

    const float* Wp[3] = {Wq, Wk, Wv};
    float* outp[3]     = {g_q, g_k, g_v};

    float acc[3][2][4][4] = {};          // [w][mt][nt][reg]

    for (int k0 = 0; k0 < EDIM; k0 += 32) {
        // x tile: 128x32, converted to tf32 bits at fill
#pragma unroll
        for (int i = 0; i < 4; i++) {
            int slot = tid + i * 256;             // 1024 float4 slots
            int m = slot >> 3, j = slot & 7;
            float4 v = *(const float4*)&x[(size_t)(m0 + m) * EDIM + k0 + 4 * j];
            uint4 u = make_uint4(f2tf(v.x), f2tf(v.y), f2tf(v.z), f2tf(v.w));
            *(uint4*)&xs[m][4 * j] = u;
        }
        // 3 weight tiles: 64x32 each
#pragma unroll
        for (int w = 0; w < 3; w++)
#pragma unroll
            for (int i = 0; i < 2; i++) {
                int slot = tid + i * 256;         // 512 float4 slots
                int d = slot >> 3, j = slot & 7;
                float4 v = *(const float4*)&Wp[w][(size_t)d * EDIM + k0 + 4 * j];
                uint4 u = make_uint4(f2tf(v.x), f2tf(v.y), f2tf(v.z), f2tf(v.w));
                *(uint4*)&ws[w][d][4 * j] = u;
            }
        __syncthreads();

#pragma unroll
        for (int ks = 0; ks < 4; ks++) {
            int k = ks * 8;
            unsigned a[2][4];
#pragma unroll
            for (int mt = 0; mt < 2; mt++) {
                int rb = wm * 32 + mt * 16;
                a[mt][0] = xs[rb + r][k + cq];
                a[mt][1] = xs[rb + r + 8][k + cq];
                a[mt][2] = xs[rb + r][k + cq + 4];
                a[mt][3] = xs[rb + r + 8][k + cq + 4];
            }
#pragma unroll
            for (int w = 0; w < 3; w++)
#pragma unroll
                for (int nt = 0; nt < 4; nt++) {
                    int nb = wn * 32 + nt * 8 + r;
                    unsigned b0 = ws[w][nb][k + cq];
                    unsigned b1 = ws[w][nb][k + cq + 4];
                    mma8(acc[w][0][nt], a[0], b0, b1);
                    mma8(acc[w][1][nt], a[1], b0, b1);
                }
        }
        __syncthreads();
    }

    // epilogue: round to tf32, store
#pragma unroll
    for (int w = 0; w < 3; w++)
#pragma unroll
        for (int mt = 0; mt < 2; mt++)
#pragma unroll
            for (int nt = 0; nt < 4; nt++) {
                int row = m0 + wm * 32 + mt * 16 + r;
                int col = wn * 32 + nt * 8 + 2 * cq;
                float* out = outp[w];
                float2 lo = make_float2(__uint_as_float(f2tf(acc[w][mt][nt][0])),
                                        __uint_as_float(f2tf(acc[w][mt][nt][1])));
                float2 hi = make_float2(__uint_as_float(f2tf(acc[w][mt][nt][2])),
                                        __uint_as_float(f2tf(acc[w][mt][nt][3])));
                *(float2*)&out[(size_t)row * DDIM + col] = lo;
                *(float2*)&out[(size_t)(row + 8) * DDIM + col] = hi;
            }
}

// ---------------------------------------------------------------------------
// Flash attention (tf32 MMA): block = (batch, 32-row q-tile), 8 warps in
// 2(m) x 4(n). Q fragments live in registers for the whole kernel (loaded
// directly from global in fragment layout). K/V/P used as raw tf32 bits —
// no cvt in the hot loop. Static smem 44.8KB, 3 blocks/SM.
// ---------------------------------------------------------------------------
__global__ __launch_bounds__(256, 3) void attn_mma(float* __restrict__ out)
{
    __shared__ unsigned Ks[KT][68];      // tf32 bits (pre-rounded in g_k)
    __shared__ unsigned Vs[KT][72];
    __shared__ float    Sp[QT][68];      // raw S, then tf32-bit P
    __shared__ float    alphas[QT];
    __shared__ float    ls[QT];

    const int tid  = threadIdx.x;
    const int lane = tid & 31;
    const int wid  = tid >> 5;
    const int wm   = wid & 1;
    const int wn   = wid >> 1;
    const int r    = lane >> 2;
    const int cq   = lane & 3;
    const int b    = blockIdx.y;
    const int qt   = gridDim.x - 1 - blockIdx.x;   // big tiles first
    const int q0   = qt * QT;
    const size_t base = (size_t)b * TSEQ * DDIM;

    const int rr = tid >> 3;             // softmax row owner
    const int gg = tid & 7;

    // Q fragments in registers: 8 k-steps x 4 regs. g_q is tf32-rounded;
    // *0.125f (exact power of 2) keeps it a valid tf32 pattern.
    unsigned qa[8][4];
    {
        const float* q0p = &g_q[base + (size_t)(q0 + wm * 16 + r) * DDIM];
        const float* q1p = q0p + 8 * DDIM;
#pragma unroll
        for (int ks = 0; ks < 8; ks++) {
            int c = ks * 8 + cq;
            qa[ks][0] = __float_as_uint(q0p[c] * 0.125f);
            qa[ks][1] = __float_as_uint(q1p[c] * 0.125f);
            qa[ks][2] = __float_as_uint(q0p[c + 4] * 0.125f);
            qa[ks][3] = __float_as_uint(q1p[c + 4] * 0.125f);
        }
    }

    float O[2][4] = {};
    float m_i = -1e30f, l_i = 0.f;

    const int ntiles = qt / 2 + 1;
    for (int kt = 0; kt < ntiles; kt++) {
        __syncthreads();                 // prev PV done reading Sp/Vs
        const int k0 = kt * KT;
#pragma unroll
        for (int i = 0; i < 4; i++) {
            int slot = tid + i * 256;    // 1024 float4 slots (64x16)
            int m = slot >> 4, j = slot & 15;
            *(uint4*)&Ks[m][4 * j] =
                *(const uint4*)&g_k[base + (size_t)(k0 + m) * DDIM + 4 * j];
            *(uint4*)&Vs[m][4 * j] =
                *(const uint4*)&g_v[base + (size_t)(k0 + m) * DDIM + 4 * j];
        }
        __syncthreads();

        // ---- S = Q * K^T ----
        float sacc[2][4] = {};
#pragma unroll
        for (int ks = 0; ks < 8; ks++) {
            int k = ks * 8;
#pragma unroll
            for (int nt = 0; nt < 2; nt++) {
                int nb = wn * 16 + nt * 8 + r;
                mma8(sacc[nt], qa[ks], Ks[nb][k + cq], Ks[nb][k + cq + 4]);
            }
        }

        // ---- mask (last tile) + write raw S ----
        const bool lastt = (kt == ntiles - 1);
#pragma unroll
        for (int nt = 0; nt < 2; nt++) {
            int row0 = wm * 16 + r;
            int col  = wn * 16 + nt * 8 + 2 * cq;
            float s0 = sacc[nt][0], s1 = sacc[nt][1];
            float s2 = sacc[nt][2], s3 = sacc[nt][3];
            if (lastt) {
                int qg0 = q0 + row0, qg1 = qg0 + 8;
                int sg0 = k0 + col,  sg1 = sg0 + 1;
                if (sg0 > qg0) s0 = -1e30f;
                if (sg1 > qg0) s1 = -1e30f;
                if (sg0 > qg1) s2 = -1e30f;
                if (sg1 > qg1) s3 = -1e30f;
            }
            *(float2*)&Sp[row0][col]     = make_float2(s0, s1);
            *(float2*)&Sp[row0 + 8][col] = make_float2(s2, s3);
        }
        __syncthreads();

        // ---- online softmax; store P as tf32 bits ----
        {
            float4 v0 = *(float4*)&Sp[rr][gg * 8];
            float4 v1 = *(float4*)&Sp[rr][gg * 8 + 4];
            float tmax = fmaxf(fmaxf(fmaxf(v0.x, v0.y), fmaxf(v0.z, v0.w)),
                               fmaxf(fmaxf(v1.x, v1.y), fmaxf(v1.z, v1.w)));
#pragma unroll
            for (int w = 4; w >= 1; w >>= 1)
                tmax = fmaxf(tmax, __shfl_xor_sync(0xffffffffu, tmax, w));
            float newm  = fmaxf(m_i, tmax);
            float alpha = fast_exp(m_i - newm);
            float p0 = fast_exp(v0.x - newm), p1 = fast_exp(v0.y - newm);
            float p2 = fast_exp(v0.z - newm), p3 = fast_exp(v0.w - newm);
            float p4 = fast_exp(v1.x - newm), p5 = fast_exp(v1.y - newm);
            float p6 = fast_exp(v1.z - newm), p7 = fast_exp(v1.w - newm);
            float tsum = ((p0 + p1) + (p2 + p3)) + ((p4 + p5) + (p6 + p7));
#pragma unroll
            for (int w = 4; w >= 1; w >>= 1)
                tsum += __shfl_xor_sync(0xffffffffu, tsum, w);
            l_i = l_i * alpha + tsum;
            m_i = newm;
            *(float4*)&Sp[rr][gg * 8] = make_float4(
                __uint_as_float(f2tf(p0)), __uint_as_float(f2tf(p1)),
                __uint_as_float(f2tf(p2)), __uint_as_float(f2tf(p3)));
            *(float4*)&Sp[rr][gg * 8 + 4] = make_float4(
                __uint_as_float(f2tf(p4)), __uint_as_float(f2tf(p5)),
                __uint_as_float(f2tf(p6)), __uint_as_float(f2tf(p7)));
            if (gg == 0) alphas[rr] = alpha;
        }
        __syncthreads();

        // ---- O = O*alpha + P*V ----
        {
            float al0 = alphas[wm * 16 + r];
            float al1 = alphas[wm * 16 + r + 8];
#pragma unroll
            for (int nt = 0; nt < 2; nt++) {
                O[nt][0] *= al0; O[nt][1] *= al0;
                O[nt][2] *= al1; O[nt][3] *= al1;
            }
#pragma unroll
            for (int ks = 0; ks < 8; ks++) {
                int k = ks * 8;
                unsigned a[4];
                int rb = wm * 16;
                a[0] = __float_as_uint(Sp[rb + r][k + cq]);
                a[1] = __float_as_uint(Sp[rb + r + 8][k + cq]);
                a[2] = __float_as_uint(Sp[rb + r][k + cq + 4]);
                a[3] = __float_as_uint(Sp[rb + r + 8][k + cq + 4]);
#pragma unroll
                for (int nt = 0; nt < 2; nt++) {
                    int nb = wn * 16 + nt * 8 + r;
                    mma8(O[nt], a, Vs[k + cq][nb], Vs[k + cq + 4][nb]);
                }
            }
        }
    }

    // epilogue
    if (gg == 0) ls[rr] = l_i;
    __syncthreads();
    float il0 = 1.f / ls[wm * 16 + r];
    float il1 = 1.f / ls[wm * 16 + r + 8];
#pragma unroll
    for (int nt = 0; nt < 2; nt++) {
        int row = q0 + wm * 16 + r;
        int col = wn * 16 + nt * 8 + 2 * cq;
        *(float2*)&out[base + (size_t)row * DDIM + col] =
            make_float2(O[nt][0] * il0, O[nt][1] * il0);
        *(float2*)&out[base + (size_t)(row + 8) * DDIM + col] =
            make_float2(O[nt][2] * il1, O[nt][3] * il1);
    }
}

// ---------------------------------------------------------------------------
// Launch
// ---------------------------------------------------------------------------
extern "C" void kernel_launch(void* const* d_in, const int* in_sizes, int n_in,
                              void* d_out, int out_size)
{
    const float* x  = (const float*)d_in[0];
    const float* Wk = (const float*)d_in[1];
    const float* Wq = (const float*)d_in[2];
    const float* Wv = (const float*)d_in[3];
    float* out = (float*)d_out;

    proj_mma<<<NROWS / 128, 256>>>(x, Wq, Wk, Wv);
    attn_mma<<<dim3(TSEQ / QT, BSZ), 256>>>(out);
}

// round 4
// speedup vs baseline: 4.1001x; 1.0733x over previous
#include <cuda_runtime.h>

#define NROWS 16384   // B*T
#define EDIM  1024
#define DDIM  64
#define BSZ   8
#define TSEQ  2048
#define QT    32      // attention q-tile rows
#define KT    64      // attention kv-tile rows

// Scratch for projected Q, K, V — stored ALREADY tf32-rounded.
__device__ float g_q[NROWS * DDIM];
__device__ float g_k[NROWS * DDIM];
__device__ float g_v[NROWS * DDIM];

// ---------------------------------------------------------------------------
// helpers
// ---------------------------------------------------------------------------
__device__ __forceinline__ unsigned f2tf(float x) {
    unsigned r;
    asm("cvt.rna.tf32.f32 %0, %1;" : "=r"(r) : "f"(x));
    return r;
}

__device__ __forceinline__ void mma8(float c[4], const unsigned a[4],
                                     unsigned b0, unsigned b1) {
    asm volatile(
        "mma.sync.aligned.m16n8k8.row.col.f32.tf32.tf32.f32 "
        "{%0,%1,%2,%3},{%4,%5,%6,%7},{%8,%9},{%0,%1,%2,%3};\n"
        : "+f"(c[0]), "+f"(c[1]), "+f"(c[2]), "+f"(c[3])
        : "r"(a[0]), "r"(a[1]), "r"(a[2]), "r"(a[3]), "r"(b0), "r"(b1));
}

__device__ __forceinline__ void cpa16(float* dst_smem, const float* src) {
    unsigned d = (unsigned)__cvta_generic_to_shared(dst_smem);
    asm volatile("cp.async.cg.shared.global [%0], [%1], 16;\n"
                 :: "r"(d), "l"(src));
}
__device__ __forceinline__ void cpa_commit() {
    asm volatile("cp.async.commit_group;\n" ::: "memory");
}
template <int N>
__device__ __forceinline__ void cpa_wait() {
    asm volatile("cp.async.wait_group %0;\n" :: "n"(N) : "memory");
}

// exp(x) for x <= ~1, FMA-pipe only. deg-5 poly, rel err < 3e-6.
__device__ __forceinline__ float fast_exp(float x) {
    float t = x * 1.4426950408889634f;
    t = fmaxf(t, -126.0f);
    float tr = t + 12582912.0f;
    float fl = tr - 12582912.0f;
    float f  = t - fl;
    float p = 1.3333558146e-3f;
    p = fmaf(p, f, 9.6181291076e-3f);
    p = fmaf(p, f, 5.5504108664e-2f);
    p = fmaf(p, f, 2.4022650696e-1f);
    p = fmaf(p, f, 6.9314718056e-1f);
    p = fmaf(p, f, 1.0f);
    int n = __float_as_int(tr) - 0x4B400000;
    float s = __int_as_float((n + 127) << 23);
    return p * s;
}

// ---------------------------------------------------------------------------
// Merged projection GEMM with 2-stage cp.async pipeline.
// One block = 128-row slab of all three outputs. Raw floats staged in smem,
// tf32 cvt at fragment load. Grid = 128 blocks (one wave).
// smem: xs2[2][128][36] + ws2[2][3][64][36] = 90KB (dynamic).
// ---------------------------------------------------------------------------
#define PROJ_SMEM ((2 * 128 * 36 + 2 * 3 * 64 * 36) * 4)

__global__ __launch_bounds__(256, 1) void proj_mma(
    const float* __restrict__ x,
    const float* __restrict__ Wq,
    const float* __restrict__ Wk,
    const float* __restrict__ Wv)
{
    extern __shared__ float dyn[];
    float (*xs2)[128][36]    = (float(*)[128][36])dyn;
    float (*ws2)[3][64][36]  = (float(*)[3][64][36])(dyn + 2 * 128 * 36);

    const int tid  = threadIdx.x;
    const int lane = tid & 31;
    const int wid  = tid >> 5;
    const int wm   = wid & 3;
    const int wn   = wid >> 2;
    const int r    = lane >> 2;
    const int cq   = lane & 3;
    const int m0   = blockIdx.x * 128;

    const float* Wp[3] = {Wq, Wk, Wv};
    float* outp[3]     = {g_q, g_k, g_v};

    // prefetch stage for k-chunk kc into buffer s
    auto prefetch = [&](int kc, int s) {
        int k0 = kc * 32;
#pragma unroll
        for (int i = 0; i < 4; i++) {
            int slot = tid + i * 256;        // 1024 float4 (128x8)
            int m = slot >> 3, j = slot & 7;
            cpa16(&xs2[s][m][4 * j], &x[(size_t)(m0 + m) * EDIM + k0 + 4 * j]);
        }
#pragma unroll
        for (int i = 0; i < 6; i++) {
            int slot = tid + i * 256;        // 1536 float4 (3x64x8)
            int w = slot >> 9, rem = slot & 511;
            int d = rem >> 3, j = rem & 7;
            cpa16(&ws2[s][w][d][4 * j], &Wp[w][(size_t)d * EDIM + k0 + 4 * j]);
        }
        cpa_commit();
    };

    float acc[3][2][4][4] = {};

    prefetch(0, 0);
    for (int kc = 0; kc < 32; kc++) {
        const int s = kc & 1;
        __syncthreads();                      // stage s^1 fully consumed
        if (kc + 1 < 32) { prefetch(kc + 1, s ^ 1); cpa_wait<1>(); }
        else             { cpa_wait<0>(); }
        __syncthreads();                      // stage s visible to all

#pragma unroll
        for (int ks = 0; ks < 4; ks++) {
            int k = ks * 8;
            unsigned a[2][4];
#pragma unroll
            for (int mt = 0; mt < 2; mt++) {
                int rb = wm * 32 + mt * 16;
                a[mt][0] = f2tf(xs2[s][rb + r][k + cq]);
                a[mt][1] = f2tf(xs2[s][rb + r + 8][k + cq]);
                a[mt][2] = f2tf(xs2[s][rb + r][k + cq + 4]);
                a[mt][3] = f2tf(xs2[s][rb + r + 8][k + cq + 4]);
            }
#pragma unroll
            for (int w = 0; w < 3; w++)
#pragma unroll
                for (int nt = 0; nt < 4; nt++) {
                    int nb = wn * 32 + nt * 8 + r;
                    unsigned b0 = f2tf(ws2[s][w][nb][k + cq]);
                    unsigned b1 = f2tf(ws2[s][w][nb][k + cq + 4]);
                    mma8(acc[w][0][nt], a[0], b0, b1);
                    mma8(acc[w][1][nt], a[1], b0, b1);
                }
        }
    }

    // epilogue: round to tf32, store
#pragma unroll
    for (int w = 0; w < 3; w++)
#pragma unroll
        for (int mt = 0; mt < 2; mt++)
#pragma unroll
            for (int nt = 0; nt < 4; nt++) {
                int row = m0 + wm * 32 + mt * 16 + r;
                int col = wn * 32 + nt * 8 + 2 * cq;
                float* out = outp[w];
                float2 lo = make_float2(__uint_as_float(f2tf(acc[w][mt][nt][0])),
                                        __uint_as_float(f2tf(acc[w][mt][nt][1])));
                float2 hi = make_float2(__uint_as_float(f2tf(acc[w][mt][nt][2])),
                                        __uint_as_float(f2tf(acc[w][mt][nt][3])));
                *(float2*)&out[(size_t)row * DDIM + col] = lo;
                *(float2*)&out[(size_t)(row + 8) * DDIM + col] = hi;
            }
}

// ---------------------------------------------------------------------------
// Flash attention: 2-stage cp.async K/V pipeline + in-register softmax.
// Q fragments in registers. m/l per-thread. Only P goes through smem.
// smem: Ks[2][64][68] + Vs[2][64][72] + Sp[32][68] + Mred/Sred[32][4] ~ 80KB.
// ---------------------------------------------------------------------------
#define ATTN_SMEM ((2 * 64 * 68 + 2 * 64 * 72 + 32 * 68 + 2 * 32 * 4) * 4)

__global__ __launch_bounds__(256, 2) void attn_mma(float* __restrict__ out)
{
    extern __shared__ float dyn[];
    float (*Ks)[KT][68] = (float(*)[KT][68])dyn;
    float (*Vs)[KT][72] = (float(*)[KT][72])(dyn + 2 * KT * 68);
    float (*Sp)[68]     = (float(*)[68])(dyn + 2 * KT * 68 + 2 * KT * 72);
    float (*Mred)[4]    = (float(*)[4])(dyn + 2 * KT * 68 + 2 * KT * 72 + QT * 68);
    float (*Sred)[4]    = (float(*)[4])(dyn + 2 * KT * 68 + 2 * KT * 72 + QT * 68 + QT * 4);

    const int tid  = threadIdx.x;
    const int lane = tid & 31;
    const int wid  = tid >> 5;
    const int wm   = wid & 1;
    const int wn   = wid >> 1;
    const int r    = lane >> 2;
    const int cq   = lane & 3;
    const int b    = blockIdx.y;
    const int qt   = gridDim.x - 1 - blockIdx.x;   // big tiles first
    const int q0   = qt * QT;
    const size_t base = (size_t)b * TSEQ * DDIM;

    const int rowA = wm * 16 + r;        // local rows owned by this thread
    const int rowB = rowA + 8;

    auto prefetch = [&](int kt, int s) {
        int k0 = kt * KT;
#pragma unroll
        for (int i = 0; i < 4; i++) {
            int slot = tid + i * 256;    // 1024 float4 (64x16)
            int m = slot >> 4, j = slot & 15;
            cpa16(&Ks[s][m][4 * j], &g_k[base + (size_t)(k0 + m) * DDIM + 4 * j]);
            cpa16(&Vs[s][m][4 * j], &g_v[base + (size_t)(k0 + m) * DDIM + 4 * j]);
        }
        cpa_commit();
    };

    // Q fragments in registers (tf32 bits; *0.125f exact)
    unsigned qa[8][4];
    {
        const float* q0p = &g_q[base + (size_t)(q0 + rowA) * DDIM];
        const float* q1p = q0p + 8 * DDIM;
#pragma unroll
        for (int ks = 0; ks < 8; ks++) {
            int c = ks * 8 + cq;
            qa[ks][0] = __float_as_uint(q0p[c] * 0.125f);
            qa[ks][1] = __float_as_uint(q1p[c] * 0.125f);
            qa[ks][2] = __float_as_uint(q0p[c + 4] * 0.125f);
            qa[ks][3] = __float_as_uint(q1p[c + 4] * 0.125f);
        }
    }

    float O[2][4] = {};
    float mA = -1e30f, mB = -1e30f, lA = 0.f, lB = 0.f;

    const int ntiles = qt / 2 + 1;
    prefetch(0, 0);

    for (int kt = 0; kt < ntiles; kt++) {
        const int s = kt & 1;
        const int k0 = kt * KT;
        __syncthreads();                 // stage s^1 + Sp fully consumed
        if (kt + 1 < ntiles) { prefetch(kt + 1, s ^ 1); cpa_wait<1>(); }
        else                 { cpa_wait<0>(); }
        __syncthreads();                 // tile kt visible to all

        // ---- S = Q * K^T ----
        float sacc[2][4] = {};
#pragma unroll
        for (int ks = 0; ks < 8; ks++) {
            int k = ks * 8;
#pragma unroll
            for (int nt = 0; nt < 2; nt++) {
                int nb = wn * 16 + nt * 8 + r;
                mma8(sacc[nt], qa[ks],
                     __float_as_uint(Ks[s][nb][k + cq]),
                     __float_as_uint(Ks[s][nb][k + cq + 4]));
            }
        }

        // ---- mask (last tile only) ----
        if (kt == ntiles - 1) {
#pragma unroll
            for (int nt = 0; nt < 2; nt++) {
                int col = wn * 16 + nt * 8 + 2 * cq;
                int qg0 = q0 + rowA, qg1 = q0 + rowB;
                int sg0 = k0 + col,  sg1 = sg0 + 1;
                if (sg0 > qg0) sacc[nt][0] = -1e30f;
                if (sg1 > qg0) sacc[nt][1] = -1e30f;
                if (sg0 > qg1) sacc[nt][2] = -1e30f;
                if (sg1 > qg1) sacc[nt][3] = -1e30f;
            }
        }

        // ---- partial row max within warp (4-lane groups share a row) ----
        {
            float pmA = fmaxf(fmaxf(sacc[0][0], sacc[0][1]),
                              fmaxf(sacc[1][0], sacc[1][1]));
            float pmB = fmaxf(fmaxf(sacc[0][2], sacc[0][3]),
                              fmaxf(sacc[1][2], sacc[1][3]));
            pmA = fmaxf(pmA, __shfl_xor_sync(0xffffffffu, pmA, 1));
            pmA = fmaxf(pmA, __shfl_xor_sync(0xffffffffu, pmA, 2));
            pmB = fmaxf(pmB, __shfl_xor_sync(0xffffffffu, pmB, 1));
            pmB = fmaxf(pmB, __shfl_xor_sync(0xffffffffu, pmB, 2));
            if (cq == 0) { Mred[rowA][wn] = pmA; Mred[rowB][wn] = pmB; }
        }
        __syncthreads();

        // ---- finish max; exponentiate in regs; write P + partial sums ----
        float alA, alB;
        {
            float4 ma4 = *(float4*)&Mred[rowA][0];
            float4 mb4 = *(float4*)&Mred[rowB][0];
            float nmA = fmaxf(mA, fmaxf(fmaxf(ma4.x, ma4.y), fmaxf(ma4.z, ma4.w)));
            float nmB = fmaxf(mB, fmaxf(fmaxf(mb4.x, mb4.y), fmaxf(mb4.z, mb4.w)));
            alA = fast_exp(mA - nmA);
            alB = fast_exp(mB - nmB);
            mA = nmA; mB = nmB;

            float pA0 = fast_exp(sacc[0][0] - nmA), pA1 = fast_exp(sacc[0][1] - nmA);
            float pA2 = fast_exp(sacc[1][0] - nmA), pA3 = fast_exp(sacc[1][1] - nmA);
            float pB0 = fast_exp(sacc[0][2] - nmB), pB1 = fast_exp(sacc[0][3] - nmB);
            float pB2 = fast_exp(sacc[1][2] - nmB), pB3 = fast_exp(sacc[1][3] - nmB);

            float psA = (pA0 + pA1) + (pA2 + pA3);
            float psB = (pB0 + pB1) + (pB2 + pB3);
            psA += __shfl_xor_sync(0xffffffffu, psA, 1);
            psA += __shfl_xor_sync(0xffffffffu, psA, 2);
            psB += __shfl_xor_sync(0xffffffffu, psB, 1);
            psB += __shfl_xor_sync(0xffffffffu, psB, 2);
            if (cq == 0) { Sred[rowA][wn] = psA; Sred[rowB][wn] = psB; }

            int c0 = wn * 16 + 2 * cq;       // nt=0 cols
            int c1 = c0 + 8;                 // nt=1 cols
            *(float2*)&Sp[rowA][c0] = make_float2(__uint_as_float(f2tf(pA0)),
                                                  __uint_as_float(f2tf(pA1)));
            *(float2*)&Sp[rowA][c1] = make_float2(__uint_as_float(f2tf(pA2)),
                                                  __uint_as_float(f2tf(pA3)));
            *(float2*)&Sp[rowB][c0] = make_float2(__uint_as_float(f2tf(pB0)),
                                                  __uint_as_float(f2tf(pB1)));
            *(float2*)&Sp[rowB][c1] = make_float2(__uint_as_float(f2tf(pB2)),
                                                  __uint_as_float(f2tf(pB3)));
        }
        __syncthreads();

        // ---- l update + O rescale + PV ----
        {
            float4 sa4 = *(float4*)&Sred[rowA][0];
            float4 sb4 = *(float4*)&Sred[rowB][0];
            lA = lA * alA + ((sa4.x + sa4.y) + (sa4.z + sa4.w));
            lB = lB * alB + ((sb4.x + sb4.y) + (sb4.z + sb4.w));
#pragma unroll
            for (int nt = 0; nt < 2; nt++) {
                O[nt][0] *= alA; O[nt][1] *= alA;
                O[nt][2] *= alB; O[nt][3] *= alB;
            }
            int rb = wm * 16;
#pragma unroll
            for (int ks = 0; ks < 8; ks++) {
                int k = ks * 8;
                unsigned a[4];
                a[0] = __float_as_uint(Sp[rb + r][k + cq]);
                a[1] = __float_as_uint(Sp[rb + r + 8][k + cq]);
                a[2] = __float_as_uint(Sp[rb + r][k + cq + 4]);
                a[3] = __float_as_uint(Sp[rb + r + 8][k + cq + 4]);
#pragma unroll
                for (int nt = 0; nt < 2; nt++) {
                    int nb = wn * 16 + nt * 8 + r;
                    mma8(O[nt], a,
                         __float_as_uint(Vs[s][k + cq][nb]),
                         __float_as_uint(Vs[s][k + cq + 4][nb]));
                }
            }
        }
    }

    // epilogue
    float ilA = 1.f / lA;
    float ilB = 1.f / lB;
#pragma unroll
    for (int nt = 0; nt < 2; nt++) {
        int row = q0 + rowA;
        int col = wn * 16 + nt * 8 + 2 * cq;
        *(float2*)&out[base + (size_t)row * DDIM + col] =
            make_float2(O[nt][0] * ilA, O[nt][1] * ilA);
        *(float2*)&out[base + (size_t)(row + 8) * DDIM + col] =
            make_float2(O[nt][2] * ilB, O[nt][3] * ilB);
    }
}

// ---------------------------------------------------------------------------
// Launch
// ---------------------------------------------------------------------------
extern "C" void kernel_launch(void* const* d_in, const int* in_sizes, int n_in,
                              void* d_out, int out_size)
{
    const float* x  = (const float*)d_in[0];
    const float* Wk = (const float*)d_in[1];
    const float* Wq = (const float*)d_in[2];
    const float* Wv = (const float*)d_in[3];
    float* out = (float*)d_out;

    cudaFuncSetAttribute(proj_mma,
                         cudaFuncAttributeMaxDynamicSharedMemorySize, PROJ_SMEM);
    cudaFuncSetAttribute(attn_mma,
                         cudaFuncAttributeMaxDynamicSharedMemorySize, ATTN_SMEM);

    proj_mma<<<NROWS / 128, 256, PROJ_SMEM>>>(x, Wq, Wk, Wv);
    attn_mma<<<dim3(TSEQ / QT, BSZ), 256, ATTN_SMEM>>>(out);
}

// round 5
// speedup vs baseline: 6.2571x; 1.5261x over previous
#include <cuda_runtime.h>
#include <cuda_fp16.h>

#define NROWS 16384   // B*T
#define EDIM  1024
#define DDIM  64
#define BSZ   8
#define TSEQ  2048
#define QT    64      // attention q-tile rows
#define KT    64      // attention kv-tile rows

// Projected tensors, fp16. q is pre-scaled by 0.125. v is stored TRANSPOSED
// per batch: g_vt[b][d][t], so PV B-fragments are contiguous half2 pairs.
__device__ __align__(16) __half g_qh[NROWS * DDIM];
__device__ __align__(16) __half g_kh[NROWS * DDIM];
__device__ __align__(16) __half g_vt[BSZ * DDIM * TSEQ];

// ---------------------------------------------------------------------------
// helpers
// ---------------------------------------------------------------------------
__device__ __forceinline__ unsigned packh2(float lo, float hi) {
    __half2 h = __floats2half2_rn(lo, hi);
    return *reinterpret_cast<unsigned*>(&h);
}

// D(16x8,f32) += A(16x16,f16) * B(16x8,f16)
__device__ __forceinline__ void mma16(float c[4],
                                      unsigned a0, unsigned a1,
                                      unsigned a2, unsigned a3,
                                      unsigned b0, unsigned b1) {
    asm volatile(
        "mma.sync.aligned.m16n8k16.row.col.f32.f16.f16.f32 "
        "{%0,%1,%2,%3},{%4,%5,%6,%7},{%8,%9},{%0,%1,%2,%3};\n"
        : "+f"(c[0]), "+f"(c[1]), "+f"(c[2]), "+f"(c[3])
        : "r"(a0), "r"(a1), "r"(a2), "r"(a3), "r"(b0), "r"(b1));
}

__device__ __forceinline__ void cpa16(void* dst_smem, const void* src) {
    unsigned d = (unsigned)__cvta_generic_to_shared(dst_smem);
    asm volatile("cp.async.cg.shared.global [%0], [%1], 16;\n"
                 :: "r"(d), "l"(src));
}
__device__ __forceinline__ void cpa_commit() {
    asm volatile("cp.async.commit_group;\n" ::: "memory");
}
template <int N>
__device__ __forceinline__ void cpa_wait() {
    asm volatile("cp.async.wait_group %0;\n" :: "n"(N) : "memory");
}

// exp(x) for x <= ~1, FMA-pipe only. deg-5 poly, rel err < 3e-6.
__device__ __forceinline__ float fast_exp(float x) {
    float t = x * 1.4426950408889634f;
    t = fmaxf(t, -126.0f);
    float tr = t + 12582912.0f;
    float fl = tr - 12582912.0f;
    float f  = t - fl;
    float p = 1.3333558146e-3f;
    p = fmaf(p, f, 9.6181291076e-3f);
    p = fmaf(p, f, 5.5504108664e-2f);
    p = fmaf(p, f, 2.4022650696e-1f);
    p = fmaf(p, f, 6.9314718056e-1f);
    p = fmaf(p, f, 1.0f);
    int n = __float_as_int(tr) - 0x4B400000;
    float s = __int_as_float((n + 127) << 23);
    return p * s;
}

// ---------------------------------------------------------------------------
// Merged projection GEMM, fp16 MMA (m16n8k16), fp32 accumulate.
// x/W staged fp32 via 2-stage cp.async; fragments packed to fp16 at load.
// One block = 128-row slab of all three outputs. Grid = 128 (one wave).
// Outputs fp16: g_qh (x0.125), g_kh, g_vt (transposed).
// ---------------------------------------------------------------------------
#define PROJ_SMEM ((2 * 128 * 40 + 2 * 3 * 64 * 40) * 4)

__global__ __launch_bounds__(256, 1) void proj_mma(
    const float* __restrict__ x,
    const float* __restrict__ Wq,
    const float* __restrict__ Wk,
    const float* __restrict__ Wv)
{
    extern __shared__ float dyn[];
    float (*xs2)[128][40]   = (float(*)[128][40])dyn;
    float (*ws2)[3][64][40] = (float(*)[3][64][40])(dyn + 2 * 128 * 40);

    const int tid  = threadIdx.x;
    const int lane = tid & 31;
    const int wid  = tid >> 5;
    const int wm   = wid & 3;
    const int wn   = wid >> 2;
    const int r    = lane >> 2;
    const int cq   = lane & 3;
    const int m0   = blockIdx.x * 128;

    const float* Wp[3] = {Wq, Wk, Wv};

    auto prefetch = [&](int kc, int s) {
        int k0 = kc * 32;
#pragma unroll
        for (int i = 0; i < 4; i++) {
            int slot = tid + i * 256;        // 1024 chunks (128x8)
            int m = slot >> 3, j = slot & 7;
            cpa16(&xs2[s][m][4 * j], &x[(size_t)(m0 + m) * EDIM + k0 + 4 * j]);
        }
#pragma unroll
        for (int i = 0; i < 6; i++) {
            int slot = tid + i * 256;        // 1536 chunks (3x64x8)
            int w = slot >> 9, rem = slot & 511;
            int d = rem >> 3, j = rem & 7;
            cpa16(&ws2[s][w][d][4 * j], &Wp[w][(size_t)d * EDIM + k0 + 4 * j]);
        }
        cpa_commit();
    };

    float acc[3][2][4][4] = {};

    prefetch(0, 0);
    for (int kc = 0; kc < 32; kc++) {
        const int s = kc & 1;
        __syncthreads();
        if (kc + 1 < 32) { prefetch(kc + 1, s ^ 1); cpa_wait<1>(); }
        else             { cpa_wait<0>(); }
        __syncthreads();

#pragma unroll
        for (int ks = 0; ks < 2; ks++) {
            int k = ks * 16;
            unsigned a[2][4];
#pragma unroll
            for (int mt = 0; mt < 2; mt++) {
                int rb = wm * 32 + mt * 16;
                float2 x0 = *(float2*)&xs2[s][rb + r][k + 2 * cq];
                float2 x1 = *(float2*)&xs2[s][rb + r + 8][k + 2 * cq];
                float2 x2 = *(float2*)&xs2[s][rb + r][k + 2 * cq + 8];
                float2 x3 = *(float2*)&xs2[s][rb + r + 8][k + 2 * cq + 8];
                a[mt][0] = packh2(x0.x, x0.y);
                a[mt][1] = packh2(x1.x, x1.y);
                a[mt][2] = packh2(x2.x, x2.y);
                a[mt][3] = packh2(x3.x, x3.y);
            }
#pragma unroll
            for (int w = 0; w < 3; w++)
#pragma unroll
                for (int nt = 0; nt < 4; nt++) {
                    int nb = wn * 32 + nt * 8 + r;
                    float2 w0 = *(float2*)&ws2[s][w][nb][k + 2 * cq];
                    float2 w1 = *(float2*)&ws2[s][w][nb][k + 2 * cq + 8];
                    unsigned b0 = packh2(w0.x, w0.y);
                    unsigned b1 = packh2(w1.x, w1.y);
                    mma16(acc[w][0][nt], a[0][0], a[0][1], a[0][2], a[0][3], b0, b1);
                    mma16(acc[w][1][nt], a[1][0], a[1][1], a[1][2], a[1][3], b0, b1);
                }
        }
    }

    // epilogue: q (scaled), k natural fp16; v transposed fp16
#pragma unroll
    for (int mt = 0; mt < 2; mt++)
#pragma unroll
        for (int nt = 0; nt < 4; nt++) {
            int row = m0 + wm * 32 + mt * 16 + r;
            int col = wn * 32 + nt * 8 + 2 * cq;
            // q
            {
                float* a = acc[0][mt][nt];
                *(__half2*)&g_qh[(size_t)row * DDIM + col] =
                    __floats2half2_rn(a[0] * 0.125f, a[1] * 0.125f);
                *(__half2*)&g_qh[(size_t)(row + 8) * DDIM + col] =
                    __floats2half2_rn(a[2] * 0.125f, a[3] * 0.125f);
            }
            // k
            {
                float* a = acc[1][mt][nt];
                *(__half2*)&g_kh[(size_t)row * DDIM + col] =
                    __floats2half2_rn(a[0], a[1]);
                *(__half2*)&g_kh[(size_t)(row + 8) * DDIM + col] =
                    __floats2half2_rn(a[2], a[3]);
            }
            // v transposed: g_vt[b][d][t]
            {
                float* a = acc[2][mt][nt];
                int bb = row >> 11;
                int tt = row & 2047;
                size_t vb = (size_t)bb * DDIM * TSEQ;
                g_vt[vb + (size_t)col * TSEQ + tt]           = __float2half_rn(a[0]);
                g_vt[vb + (size_t)(col + 1) * TSEQ + tt]     = __float2half_rn(a[1]);
                g_vt[vb + (size_t)col * TSEQ + tt + 8]       = __float2half_rn(a[2]);
                g_vt[vb + (size_t)(col + 1) * TSEQ + tt + 8] = __float2half_rn(a[3]);
            }
        }
}

// ---------------------------------------------------------------------------
// Flash attention, fp16 MMA. 128 threads = 4 warps; warp w owns q-rows
// [16w, 16w+16) x ALL 64 kv cols -> softmax is warp-local (no smem, no
// barrier) and the fp32 S fragment converts in-register to the fp16 PV
// A-fragment (FA2 trick). 2-stage cp.async K/Vt pipeline; only 2 barriers
// per tile. Static smem 36KB, 4 blocks/SM.
// ---------------------------------------------------------------------------
__global__ __launch_bounds__(128, 4) void attn_mma(float* __restrict__ out)
{
    __shared__ __align__(16) __half Ks[2][KT][72];    // [kv][d], pad 72
    __shared__ __align__(16) __half Vt[2][DDIM][72];  // [d][kv], pad 72

    const int tid  = threadIdx.x;
    const int lane = tid & 31;
    const int w    = tid >> 5;     // warp id = row strip
    const int r    = lane >> 2;
    const int cq   = lane & 3;
    const int b    = blockIdx.y;
    const int qt   = gridDim.x - 1 - blockIdx.x;   // big tiles first
    const int q0   = qt * QT;
    const size_t base  = (size_t)b * TSEQ * DDIM;
    const size_t vbase = (size_t)b * DDIM * TSEQ;

    auto prefetch = [&](int kt, int s) {
        int k0 = kt * KT;
#pragma unroll
        for (int i = 0; i < 4; i++) {
            int slot = tid + i * 128;      // 512 chunks (64 rows x 8)
            int m = slot >> 3, j = slot & 7;
            cpa16(&Ks[s][m][8 * j], &g_kh[base + (size_t)(k0 + m) * DDIM + 8 * j]);
            cpa16(&Vt[s][m][8 * j], &g_vt[vbase + (size_t)m * TSEQ + k0 + 8 * j]);
        }
        cpa_commit();
    };

    // Q fragments (fp16, pre-scaled): 4 k-chunks x 4 regs
    unsigned qa[4][4];
    {
        const __half* q0p = &g_qh[base + (size_t)(q0 + 16 * w + r) * DDIM];
        const __half* q1p = q0p + 8 * DDIM;
#pragma unroll
        for (int kc = 0; kc < 4; kc++) {
            int c = 16 * kc + 2 * cq;
            qa[kc][0] = *(const unsigned*)&q0p[c];
            qa[kc][1] = *(const unsigned*)&q1p[c];
            qa[kc][2] = *(const unsigned*)&q0p[c + 8];
            qa[kc][3] = *(const unsigned*)&q1p[c + 8];
        }
    }

    float O[8][4] = {};
    float mA = -1e30f, mB = -1e30f, lA = 0.f, lB = 0.f;

    const int ntiles = qt + 1;
    prefetch(0, 0);

    for (int kt = 0; kt < ntiles; kt++) {
        const int s  = kt & 1;
        const int k0 = kt * KT;
        __syncthreads();                       // stage s^1 free to overwrite
        if (kt + 1 < ntiles) { prefetch(kt + 1, s ^ 1); cpa_wait<1>(); }
        else                 { cpa_wait<0>(); }
        __syncthreads();                       // stage s visible

        // ---- S = Q * K^T : warp computes 16 x 64 ----
        float sacc[8][4] = {};
#pragma unroll
        for (int kc = 0; kc < 4; kc++) {
#pragma unroll
            for (int nt = 0; nt < 8; nt++) {
                unsigned b0 = *(const unsigned*)&Ks[s][nt * 8 + r][16 * kc + 2 * cq];
                unsigned b1 = *(const unsigned*)&Ks[s][nt * 8 + r][16 * kc + 2 * cq + 8];
                mma16(sacc[nt], qa[kc][0], qa[kc][1], qa[kc][2], qa[kc][3], b0, b1);
            }
        }

        // ---- causal mask (diagonal tile only) ----
        if (kt == qt) {
            int rowg = q0 + 16 * w + r;
#pragma unroll
            for (int nt = 0; nt < 8; nt++) {
                int col = k0 + nt * 8 + 2 * cq;
                if (col     > rowg)     sacc[nt][0] = -1e30f;
                if (col + 1 > rowg)     sacc[nt][1] = -1e30f;
                if (col     > rowg + 8) sacc[nt][2] = -1e30f;
                if (col + 1 > rowg + 8) sacc[nt][3] = -1e30f;
            }
        }

        // ---- warp-local online softmax; P packed to fp16 in registers ----
        unsigned phA[8], phB[8];
        {
            float pmA = -1e30f, pmB = -1e30f;
#pragma unroll
            for (int nt = 0; nt < 8; nt++) {
                pmA = fmaxf(pmA, fmaxf(sacc[nt][0], sacc[nt][1]));
                pmB = fmaxf(pmB, fmaxf(sacc[nt][2], sacc[nt][3]));
            }
            pmA = fmaxf(pmA, __shfl_xor_sync(0xffffffffu, pmA, 1));
            pmA = fmaxf(pmA, __shfl_xor_sync(0xffffffffu, pmA, 2));
            pmB = fmaxf(pmB, __shfl_xor_sync(0xffffffffu, pmB, 1));
            pmB = fmaxf(pmB, __shfl_xor_sync(0xffffffffu, pmB, 2));
            float nmA = fmaxf(mA, pmA), nmB = fmaxf(mB, pmB);
            float alA = fast_exp(mA - nmA), alB = fast_exp(mB - nmB);
            mA = nmA; mB = nmB;

            float sA = 0.f, sB = 0.f;
#pragma unroll
            for (int nt = 0; nt < 8; nt++) {
                float p0 = fast_exp(sacc[nt][0] - nmA);
                float p1 = fast_exp(sacc[nt][1] - nmA);
                float p2 = fast_exp(sacc[nt][2] - nmB);
                float p3 = fast_exp(sacc[nt][3] - nmB);
                sA += p0 + p1; sB += p2 + p3;
                phA[nt] = packh2(p0, p1);
                phB[nt] = packh2(p2, p3);
            }
            sA += __shfl_xor_sync(0xffffffffu, sA, 1);
            sA += __shfl_xor_sync(0xffffffffu, sA, 2);
            sB += __shfl_xor_sync(0xffffffffu, sB, 1);
            sB += __shfl_xor_sync(0xffffffffu, sB, 2);
            lA = lA * alA + sA;
            lB = lB * alB + sB;
#pragma unroll
            for (int nt = 0; nt < 8; nt++) {
                O[nt][0] *= alA; O[nt][1] *= alA;
                O[nt][2] *= alB; O[nt][3] *= alB;
            }
        }

        // ---- O += P * V : A-fragments are the packed S registers ----
#pragma unroll
        for (int kc = 0; kc < 4; kc++) {
            unsigned a0 = phA[2 * kc],     a1 = phB[2 * kc];
            unsigned a2 = phA[2 * kc + 1], a3 = phB[2 * kc + 1];
#pragma unroll
            for (int nt = 0; nt < 8; nt++) {
                unsigned b0 = *(const unsigned*)&Vt[s][nt * 8 + r][16 * kc + 2 * cq];
                unsigned b1 = *(const unsigned*)&Vt[s][nt * 8 + r][16 * kc + 2 * cq + 8];
                mma16(O[nt], a0, a1, a2, a3, b0, b1);
            }
        }
    }

    // ---- epilogue ----
    float ilA = 1.f / lA, ilB = 1.f / lB;
    int rowg = q0 + 16 * w + r;
#pragma unroll
    for (int nt = 0; nt < 8; nt++) {
        int col = nt * 8 + 2 * cq;
        *(float2*)&out[base + (size_t)rowg * DDIM + col] =
            make_float2(O[nt][0] * ilA, O[nt][1] * ilA);
        *(float2*)&out[base + (size_t)(rowg + 8) * DDIM + col] =
            make_float2(O[nt][2] * ilB, O[nt][3] * ilB);
    }
}

// ---------------------------------------------------------------------------
// Launch
// ---------------------------------------------------------------------------
extern "C" void kernel_launch(void* const* d_in, const int* in_sizes, int n_in,
                              void* d_out, int out_size)
{
    const float* x  = (const float*)d_in[0];
    const float* Wk = (const float*)d_in[1];
    const float* Wq = (const float*)d_in[2];
    const float* Wv = (const float*)d_in[3];
    float* out = (float*)d_out;

    cudaFuncSetAttribute(proj_mma,
                         cudaFuncAttributeMaxDynamicSharedMemorySize, PROJ_SMEM);

    proj_mma<<<NROWS / 128, 256, PROJ_SMEM>>>(x, Wq, Wk, Wv);
    attn_mma<<<dim3(TSEQ / QT, BSZ), 128>>>(out);
}

// round 6
// speedup vs baseline: 8.4601x; 1.3521x over previous
#include <cuda_runtime.h>
#include <cuda_fp16.h>

#define NROWS 16384   // B*T
#define EDIM  1024
#define DDIM  64
#define BSZ   8
#define TSEQ  2048
#define QT    64      // attention q-tile rows
#define KT    64      // attention kv-tile rows
#define CKT   8       // kv tiles per chunk (512 keys)
#define NJOB  80      // jobs per batch = sum ceil((qt+1)/8), qt=0..31

// Projected tensors, fp16. q pre-scaled by 0.125. v stored transposed
// per batch: g_vt[b][d][t].
__device__ __align__(16) __half g_qh[NROWS * DDIM];
__device__ __align__(16) __half g_kh[NROWS * DDIM];
__device__ __align__(16) __half g_vt[BSZ * DDIM * TSEQ];

// Split-KV partials: [b][qt][chunk] -> unnormalized O (64x64), row m, row l
__device__ float g_part[(size_t)BSZ * 32 * 4 * 64 * 64];   // 16.8 MB
__device__ float g_pm[BSZ * 32 * 4 * 64];
__device__ float g_pl[BSZ * 32 * 4 * 64];

// ---------------------------------------------------------------------------
// helpers
// ---------------------------------------------------------------------------
__device__ __forceinline__ unsigned packh2(float lo, float hi) {
    __half2 h = __floats2half2_rn(lo, hi);
    return *reinterpret_cast<unsigned*>(&h);
}

__device__ __forceinline__ void mma16(float c[4],
                                      unsigned a0, unsigned a1,
                                      unsigned a2, unsigned a3,
                                      unsigned b0, unsigned b1) {
    asm volatile(
        "mma.sync.aligned.m16n8k16.row.col.f32.f16.f16.f32 "
        "{%0,%1,%2,%3},{%4,%5,%6,%7},{%8,%9},{%0,%1,%2,%3};\n"
        : "+f"(c[0]), "+f"(c[1]), "+f"(c[2]), "+f"(c[3])
        : "r"(a0), "r"(a1), "r"(a2), "r"(a3), "r"(b0), "r"(b1));
}

__device__ __forceinline__ void cpa16(void* dst_smem, const void* src) {
    unsigned d = (unsigned)__cvta_generic_to_shared(dst_smem);
    asm volatile("cp.async.cg.shared.global [%0], [%1], 16;\n"
                 :: "r"(d), "l"(src));
}
__device__ __forceinline__ void cpa_commit() {
    asm volatile("cp.async.commit_group;\n" ::: "memory");
}
template <int N>
__device__ __forceinline__ void cpa_wait() {
    asm volatile("cp.async.wait_group %0;\n" :: "n"(N) : "memory");
}

// exp(x) for x <= ~1, FMA-pipe only. deg-5 poly, rel err < 3e-6.
__device__ __forceinline__ float fast_exp(float x) {
    float t = x * 1.4426950408889634f;
    t = fmaxf(t, -126.0f);
    float tr = t + 12582912.0f;
    float fl = tr - 12582912.0f;
    float f  = t - fl;
    float p = 1.3333558146e-3f;
    p = fmaf(p, f, 9.6181291076e-3f);
    p = fmaf(p, f, 5.5504108664e-2f);
    p = fmaf(p, f, 2.4022650696e-1f);
    p = fmaf(p, f, 6.9314718056e-1f);
    p = fmaf(p, f, 1.0f);
    int n = __float_as_int(tr) - 0x4B400000;
    float s = __int_as_float((n + 127) << 23);
    return p * s;
}

// ---------------------------------------------------------------------------
// Merged projection GEMM, fp16 MMA, 3-stage cp.async pipeline, ONE barrier
// per k-chunk. One block = 128-row slab of q,k,v. Grid = 128 (one wave).
// smem: 3 x (128x40 + 3x64x40) floats = 153.6 KB.
// ---------------------------------------------------------------------------
#define PROJ_STAGE (128 * 40 + 3 * 64 * 40)
#define PROJ_SMEM  (3 * PROJ_STAGE * 4)

__global__ __launch_bounds__(256, 1) void proj_mma(
    const float* __restrict__ x,
    const float* __restrict__ Wq,
    const float* __restrict__ Wk,
    const float* __restrict__ Wv)
{
    extern __shared__ float dyn[];

    const int tid  = threadIdx.x;
    const int lane = tid & 31;
    const int wid  = tid >> 5;
    const int wm   = wid & 3;
    const int wn   = wid >> 2;
    const int r    = lane >> 2;
    const int cq   = lane & 3;
    const int m0   = blockIdx.x * 128;

    const float* Wp[3] = {Wq, Wk, Wv};

    auto prefetch = [&](int kc, int s) {
        float (*xs)[40] = (float(*)[40])(dyn + (size_t)s * PROJ_STAGE);
        float (*ws)[64][40] = (float(*)[64][40])(dyn + (size_t)s * PROJ_STAGE + 128 * 40);
        int k0 = kc * 32;
#pragma unroll
        for (int i = 0; i < 4; i++) {
            int slot = tid + i * 256;
            int m = slot >> 3, j = slot & 7;
            cpa16(&xs[m][4 * j], &x[(size_t)(m0 + m) * EDIM + k0 + 4 * j]);
        }
#pragma unroll
        for (int i = 0; i < 6; i++) {
            int slot = tid + i * 256;
            int w = slot >> 9, rem = slot & 511;
            int d = rem >> 3, j = rem & 7;
            cpa16(&ws[w][d][4 * j], &Wp[w][(size_t)d * EDIM + k0 + 4 * j]);
        }
        cpa_commit();
    };

    float acc[3][2][4][4] = {};

    prefetch(0, 0);
    prefetch(1, 1);
    for (int kc = 0; kc < 32; kc++) {
        const int s = kc % 3;
        cpa_wait<1>();                 // chunk kc arrived
        __syncthreads();               // all warps done with slot (kc-1)%3
        if (kc + 2 < 32) prefetch(kc + 2, (kc + 2) % 3);

        float (*xs)[40] = (float(*)[40])(dyn + (size_t)s * PROJ_STAGE);
        float (*ws)[64][40] = (float(*)[64][40])(dyn + (size_t)s * PROJ_STAGE + 128 * 40);

#pragma unroll
        for (int ks = 0; ks < 2; ks++) {
            int k = ks * 16;
            unsigned a[2][4];
#pragma unroll
            for (int mt = 0; mt < 2; mt++) {
                int rb = wm * 32 + mt * 16;
                float2 x0 = *(float2*)&xs[rb + r][k + 2 * cq];
                float2 x1 = *(float2*)&xs[rb + r + 8][k + 2 * cq];
                float2 x2 = *(float2*)&xs[rb + r][k + 2 * cq + 8];
                float2 x3 = *(float2*)&xs[rb + r + 8][k + 2 * cq + 8];
                a[mt][0] = packh2(x0.x, x0.y);
                a[mt][1] = packh2(x1.x, x1.y);
                a[mt][2] = packh2(x2.x, x2.y);
                a[mt][3] = packh2(x3.x, x3.y);
            }
#pragma unroll
            for (int w = 0; w < 3; w++)
#pragma unroll
                for (int nt = 0; nt < 4; nt++) {
                    int nb = wn * 32 + nt * 8 + r;
                    float2 w0 = *(float2*)&ws[w][nb][k + 2 * cq];
                    float2 w1 = *(float2*)&ws[w][nb][k + 2 * cq + 8];
                    unsigned b0 = packh2(w0.x, w0.y);
                    unsigned b1 = packh2(w1.x, w1.y);
                    mma16(acc[w][0][nt], a[0][0], a[0][1], a[0][2], a[0][3], b0, b1);
                    mma16(acc[w][1][nt], a[1][0], a[1][1], a[1][2], a[1][3], b0, b1);
                }
        }
    }

#pragma unroll
    for (int mt = 0; mt < 2; mt++)
#pragma unroll
        for (int nt = 0; nt < 4; nt++) {
            int row = m0 + wm * 32 + mt * 16 + r;
            int col = wn * 32 + nt * 8 + 2 * cq;
            {
                float* a = acc[0][mt][nt];
                *(__half2*)&g_qh[(size_t)row * DDIM + col] =
                    __floats2half2_rn(a[0] * 0.125f, a[1] * 0.125f);
                *(__half2*)&g_qh[(size_t)(row + 8) * DDIM + col] =
                    __floats2half2_rn(a[2] * 0.125f, a[3] * 0.125f);
            }
            {
                float* a = acc[1][mt][nt];
                *(__half2*)&g_kh[(size_t)row * DDIM + col] =
                    __floats2half2_rn(a[0], a[1]);
                *(__half2*)&g_kh[(size_t)(row + 8) * DDIM + col] =
                    __floats2half2_rn(a[2], a[3]);
            }
            {
                float* a = acc[2][mt][nt];
                int bb = row >> 11;
                int tt = row & 2047;
                size_t vb = (size_t)bb * DDIM * TSEQ;
                g_vt[vb + (size_t)col * TSEQ + tt]           = __float2half_rn(a[0]);
                g_vt[vb + (size_t)(col + 1) * TSEQ + tt]     = __float2half_rn(a[1]);
                g_vt[vb + (size_t)col * TSEQ + tt + 8]       = __float2half_rn(a[2]);
                g_vt[vb + (size_t)(col + 1) * TSEQ + tt + 8] = __float2half_rn(a[3]);
            }
        }
}

// ---------------------------------------------------------------------------
// Split-KV flash attention. Job = (batch, q-tile, kv-chunk of <=8 KT-tiles).
// 80 jobs/batch -> 640 blocks. Single-chunk q-tiles (qt<8) write out
// directly; others write unnormalized partials + (m,l) for the merge kernel.
// ---------------------------------------------------------------------------
__global__ __launch_bounds__(128, 4) void attn_split(float* __restrict__ out)
{
    __shared__ __align__(16) __half Ks[2][KT][72];
    __shared__ __align__(16) __half Vt[2][DDIM][72];

    const int tid  = threadIdx.x;
    const int lane = tid & 31;
    const int w    = tid >> 5;
    const int r    = lane >> 2;
    const int cq   = lane & 3;
    const int b    = blockIdx.y;

    // job decode (reversed so 8-tile chunks launch first)
    const int j = NJOB - 1 - blockIdx.x;
    int qt, ck;
    if (j < 8)       { qt = j;                   ck = 0; }
    else if (j < 24) { qt = 8  + ((j - 8)  >> 1); ck = (j - 8)  & 1; }
    else if (j < 48) { qt = 16 + (j - 24) / 3;    ck = (j - 24) % 3; }
    else             { qt = 24 + ((j - 48) >> 2); ck = (j - 48) & 3; }
    const int nch  = qt / CKT + 1;
    const int kbeg = ck * CKT;
    const int kend = min(kbeg + CKT, qt + 1);

    const int q0 = qt * QT;
    const size_t base  = (size_t)b * TSEQ * DDIM;
    const size_t vbase = (size_t)b * DDIM * TSEQ;

    auto prefetch = [&](int kt, int s) {
        int k0 = kt * KT;
#pragma unroll
        for (int i = 0; i < 4; i++) {
            int slot = tid + i * 128;
            int m = slot >> 3, jj = slot & 7;
            cpa16(&Ks[s][m][8 * jj], &g_kh[base + (size_t)(k0 + m) * DDIM + 8 * jj]);
            cpa16(&Vt[s][m][8 * jj], &g_vt[vbase + (size_t)m * TSEQ + k0 + 8 * jj]);
        }
        cpa_commit();
    };

    // Q fragments (fp16, pre-scaled)
    unsigned qa[4][4];
    {
        const __half* q0p = &g_qh[base + (size_t)(q0 + 16 * w + r) * DDIM];
        const __half* q1p = q0p + 8 * DDIM;
#pragma unroll
        for (int kc = 0; kc < 4; kc++) {
            int c = 16 * kc + 2 * cq;
            qa[kc][0] = *(const unsigned*)&q0p[c];
            qa[kc][1] = *(const unsigned*)&q1p[c];
            qa[kc][2] = *(const unsigned*)&q0p[c + 8];
            qa[kc][3] = *(const unsigned*)&q1p[c + 8];
        }
    }

    float O[8][4] = {};
    float mA = -1e30f, mB = -1e30f, lA = 0.f, lB = 0.f;

    prefetch(kbeg, 0);

    for (int kt = kbeg; kt < kend; kt++) {
        const int s  = (kt - kbeg) & 1;
        const int k0 = kt * KT;
        __syncthreads();
        if (kt + 1 < kend) { prefetch(kt + 1, s ^ 1); cpa_wait<1>(); }
        else               { cpa_wait<0>(); }
        __syncthreads();

        // ---- S = Q * K^T ----
        float sacc[8][4] = {};
#pragma unroll
        for (int kc = 0; kc < 4; kc++) {
#pragma unroll
            for (int nt = 0; nt < 8; nt++) {
                unsigned b0 = *(const unsigned*)&Ks[s][nt * 8 + r][16 * kc + 2 * cq];
                unsigned b1 = *(const unsigned*)&Ks[s][nt * 8 + r][16 * kc + 2 * cq + 8];
                mma16(sacc[nt], qa[kc][0], qa[kc][1], qa[kc][2], qa[kc][3], b0, b1);
            }
        }

        // ---- causal mask (diagonal tile only) ----
        if (kt == qt) {
            int rowg = q0 + 16 * w + r;
#pragma unroll
            for (int nt = 0; nt < 8; nt++) {
                int col = k0 + nt * 8 + 2 * cq;
                if (col     > rowg)     sacc[nt][0] = -1e30f;
                if (col + 1 > rowg)     sacc[nt][1] = -1e30f;
                if (col     > rowg + 8) sacc[nt][2] = -1e30f;
                if (col + 1 > rowg + 8) sacc[nt][3] = -1e30f;
            }
        }

        // ---- warp-local online softmax; P packed in registers ----
        unsigned phA[8], phB[8];
        {
            float pmA = -1e30f, pmB = -1e30f;
#pragma unroll
            for (int nt = 0; nt < 8; nt++) {
                pmA = fmaxf(pmA, fmaxf(sacc[nt][0], sacc[nt][1]));
                pmB = fmaxf(pmB, fmaxf(sacc[nt][2], sacc[nt][3]));
            }
            pmA = fmaxf(pmA, __shfl_xor_sync(0xffffffffu, pmA, 1));
            pmA = fmaxf(pmA, __shfl_xor_sync(0xffffffffu, pmA, 2));
            pmB = fmaxf(pmB, __shfl_xor_sync(0xffffffffu, pmB, 1));
            pmB = fmaxf(pmB, __shfl_xor_sync(0xffffffffu, pmB, 2));
            float nmA = fmaxf(mA, pmA), nmB = fmaxf(mB, pmB);
            float alA = fast_exp(mA - nmA), alB = fast_exp(mB - nmB);
            mA = nmA; mB = nmB;

            float sA = 0.f, sB = 0.f;
#pragma unroll
            for (int nt = 0; nt < 8; nt++) {
                float p0 = fast_exp(sacc[nt][0] - nmA);
                float p1 = fast_exp(sacc[nt][1] - nmA);
                float p2 = fast_exp(sacc[nt][2] - nmB);
                float p3 = fast_exp(sacc[nt][3] - nmB);
                sA += p0 + p1; sB += p2 + p3;
                phA[nt] = packh2(p0, p1);
                phB[nt] = packh2(p2, p3);
            }
            sA += __shfl_xor_sync(0xffffffffu, sA, 1);
            sA += __shfl_xor_sync(0xffffffffu, sA, 2);
            sB += __shfl_xor_sync(0xffffffffu, sB, 1);
            sB += __shfl_xor_sync(0xffffffffu, sB, 2);
            lA = lA * alA + sA;
            lB = lB * alB + sB;
#pragma unroll
            for (int nt = 0; nt < 8; nt++) {
                O[nt][0] *= alA; O[nt][1] *= alA;
                O[nt][2] *= alB; O[nt][3] *= alB;
            }
        }

        // ---- O += P * V ----
#pragma unroll
        for (int kc = 0; kc < 4; kc++) {
            unsigned a0 = phA[2 * kc],     a1 = phB[2 * kc];
            unsigned a2 = phA[2 * kc + 1], a3 = phB[2 * kc + 1];
#pragma unroll
            for (int nt = 0; nt < 8; nt++) {
                unsigned b0 = *(const unsigned*)&Vt[s][nt * 8 + r][16 * kc + 2 * cq];
                unsigned b1 = *(const unsigned*)&Vt[s][nt * 8 + r][16 * kc + 2 * cq + 8];
                mma16(O[nt], a0, a1, a2, a3, b0, b1);
            }
        }
    }

    // ---- epilogue ----
    if (nch == 1) {
        float ilA = 1.f / lA, ilB = 1.f / lB;
        int rowg = q0 + 16 * w + r;
#pragma unroll
        for (int nt = 0; nt < 8; nt++) {
            int col = nt * 8 + 2 * cq;
            *(float2*)&out[base + (size_t)rowg * DDIM + col] =
                make_float2(O[nt][0] * ilA, O[nt][1] * ilA);
            *(float2*)&out[base + (size_t)(rowg + 8) * DDIM + col] =
                make_float2(O[nt][2] * ilB, O[nt][3] * ilB);
        }
    } else {
        const size_t slot = ((size_t)b * 32 + qt) * 4 + ck;
        float* P = g_part + slot * (64 * 64);
        int rowL = 16 * w + r;
#pragma unroll
        for (int nt = 0; nt < 8; nt++) {
            int col = nt * 8 + 2 * cq;
            *(float2*)&P[(size_t)rowL * 64 + col]       = make_float2(O[nt][0], O[nt][1]);
            *(float2*)&P[(size_t)(rowL + 8) * 64 + col] = make_float2(O[nt][2], O[nt][3]);
        }
        if (cq == 0) {
            g_pm[slot * 64 + rowL]     = mA;
            g_pl[slot * 64 + rowL]     = lA;
            g_pm[slot * 64 + rowL + 8] = mB;
            g_pl[slot * 64 + rowL + 8] = lB;
        }
    }
}

// ---------------------------------------------------------------------------
// Merge kernel: combine 2..4 KV-chunk partials for q-tiles qt >= 8.
// Grid (24, 8), 256 threads: thread owns one row x 16 d-cols.
// ---------------------------------------------------------------------------
__global__ __launch_bounds__(256) void attn_merge(float* __restrict__ out)
{
    const int qt  = 8 + blockIdx.x;
    const int b   = blockIdx.y;
    const int nch = qt / CKT + 1;
    const int tid = threadIdx.x;
    const int row = tid >> 2;
    const int cg  = (tid & 3) * 16;

    const size_t slot0 = ((size_t)b * 32 + qt) * 4;

    float m[4], l[4];
    float M = -1e30f;
#pragma unroll
    for (int c = 0; c < 4; c++) {
        if (c < nch) {
            m[c] = g_pm[(slot0 + c) * 64 + row];
            l[c] = g_pl[(slot0 + c) * 64 + row];
            M = fmaxf(M, m[c]);
        }
    }
    float L = 0.f, sc[4];
#pragma unroll
    for (int c = 0; c < 4; c++) {
        if (c < nch) {
            sc[c] = fast_exp(m[c] - M);
            L += sc[c] * l[c];
        }
    }

    float4 acc[4] = {};
#pragma unroll
    for (int c = 0; c < 4; c++) {
        if (c < nch) {
            const float* P = g_part + (slot0 + c) * (64 * 64) + (size_t)row * 64 + cg;
            float wgt = sc[c];
#pragma unroll
            for (int i = 0; i < 4; i++) {
                float4 v = *(const float4*)&P[4 * i];
                acc[i].x = fmaf(wgt, v.x, acc[i].x);
                acc[i].y = fmaf(wgt, v.y, acc[i].y);
                acc[i].z = fmaf(wgt, v.z, acc[i].z);
                acc[i].w = fmaf(wgt, v.w, acc[i].w);
            }
        }
    }

    float invL = 1.f / L;
    size_t o = ((size_t)b * TSEQ + qt * QT + row) * DDIM + cg;
#pragma unroll
    for (int i = 0; i < 4; i++) {
        *(float4*)&out[o + 4 * i] = make_float4(acc[i].x * invL, acc[i].y * invL,
                                                acc[i].z * invL, acc[i].w * invL);
    }
}

// ---------------------------------------------------------------------------
// Launch
// ---------------------------------------------------------------------------
extern "C" void kernel_launch(void* const* d_in, const int* in_sizes, int n_in,
                              void* d_out, int out_size)
{
    const float* x  = (const float*)d_in[0];
    const float* Wk = (const float*)d_in[1];
    const float* Wq = (const float*)d_in[2];
    const float* Wv = (const float*)d_in[3];
    float* out = (float*)d_out;

    cudaFuncSetAttribute(proj_mma,
                         cudaFuncAttributeMaxDynamicSharedMemorySize, PROJ_SMEM);

    proj_mma<<<NROWS / 128, 256, PROJ_SMEM>>>(x, Wq, Wk, Wv);
    attn_split<<<dim3(NJOB, BSZ), 128>>>(out);
    attn_merge<<<dim3(24, BSZ), 256>>>(out);
}